// round 3
// baseline (speedup 1.0000x reference)
#include <cuda_runtime.h>
#include <stdint.h>

#define N_NODES 50000
#define N_EDGES 625000
#define IN_DIMS 128

// Scratch: per-node partial dot products (allocation-free device globals).
__device__ float g_s[N_NODES];  // x[i] . W_src
__device__ float g_t[N_NODES];  // x[i] . W_dst

// One warp per node row. Lane l handles elements [4l, 4l+4).
__global__ void node_dot_kernel(const float* __restrict__ x,
                                const float* __restrict__ W,
                                int n_nodes) {
    int warp = (int)((blockIdx.x * blockDim.x + threadIdx.x) >> 5);
    int lane = threadIdx.x & 31;
    if (warp >= n_nodes) return;

    const float4 xa = reinterpret_cast<const float4*>(x + (size_t)warp * IN_DIMS)[lane];
    const float4 ws = reinterpret_cast<const float4*>(W)[lane];             // W_src
    const float4 wd = reinterpret_cast<const float4*>(W + IN_DIMS)[lane];   // W_dst

    float ps = xa.x * ws.x + xa.y * ws.y + xa.z * ws.z + xa.w * ws.w;
    float pt = xa.x * wd.x + xa.y * wd.y + xa.z * wd.z + xa.w * wd.w;

    #pragma unroll
    for (int o = 16; o > 0; o >>= 1) {
        ps += __shfl_xor_sync(0xffffffffu, ps, o);
        pt += __shfl_xor_sync(0xffffffffu, pt, o);
    }
    if (lane == 0) {
        g_s[warp] = ps;
        g_t[warp] = pt;
    }
}

// 4 edges per thread: out[e] = s[src[e]] + t[dst[e]] + b
// edge_index is int32 (JAX downgrades int64 randint with x64 disabled).
__global__ void edge_gather_kernel(const int* __restrict__ ei,
                                   const float* __restrict__ b,
                                   float* __restrict__ out,
                                   int n_edges) {
    int t = blockIdx.x * blockDim.x + threadIdx.x;
    int e = t * 4;
    if (e >= n_edges) return;
    float bias = __ldg(b);

    if (e + 4 <= n_edges) {
        int4 si = *reinterpret_cast<const int4*>(ei + e);
        int4 di = *reinterpret_cast<const int4*>(ei + n_edges + e);
        float4 r;
        r.x = g_s[si.x] + g_t[di.x] + bias;
        r.y = g_s[si.y] + g_t[di.y] + bias;
        r.z = g_s[si.z] + g_t[di.z] + bias;
        r.w = g_s[si.w] + g_t[di.w] + bias;
        *reinterpret_cast<float4*>(out + e) = r;
    } else {
        for (int k = e; k < n_edges; k++) {
            out[k] = g_s[ei[k]] + g_t[ei[n_edges + k]] + bias;
        }
    }
}

extern "C" void kernel_launch(void* const* d_in, const int* in_sizes, int n_in,
                              void* d_out, int out_size) {
    const float* x   = (const float*)d_in[0];   // [N_NODES, 128] f32
    const int*   ei  = (const int*)d_in[1];     // [2, N_EDGES] int32
    const float* W   = (const float*)d_in[2];   // [1, 256] f32
    const float* b   = (const float*)d_in[3];   // [1] f32
    float*       out = (float*)d_out;           // [N_EDGES] f32

    // Node pass: 8 warps per block (256 threads), one warp per row.
    {
        int warps_per_block = 8;
        int threads = warps_per_block * 32;
        int blocks = (N_NODES + warps_per_block - 1) / warps_per_block;
        node_dot_kernel<<<blocks, threads>>>(x, W, N_NODES);
    }
    // Edge pass: 4 edges per thread, vectorized index/output access.
    {
        int threads = 256;
        int edges_per_block = threads * 4;
        int blocks = (N_EDGES + edges_per_block - 1) / edges_per_block;
        edge_gather_kernel<<<blocks, threads>>>(ei, b, out, N_EDGES);
    }
}

// round 4
// speedup vs baseline: 1.1552x; 1.1552x over previous
#include <cuda_runtime.h>
#include <stdint.h>

#define N_NODES 50000
#define N_EDGES 625000
#define IN_DIMS 128
#define ROWS_PER_WARP 4

// Scratch: per-node partial dot products (allocation-free device globals).
__device__ float g_s[N_NODES];  // x[i] . W_src
__device__ float g_t[N_NODES];  // x[i] . W_dst

// Each warp handles 4 rows; all 4 row-loads issued upfront for MLP.
// Lane l covers elements [4l, 4l+4) of each row.
__global__ void node_dot_kernel(const float* __restrict__ x,
                                const float* __restrict__ W,
                                int n_nodes) {
    int warp = (int)((blockIdx.x * blockDim.x + threadIdx.x) >> 5);
    int lane = threadIdx.x & 31;
    int row0 = warp * ROWS_PER_WARP;
    if (row0 >= n_nodes) return;

    const float4 ws = reinterpret_cast<const float4*>(W)[lane];             // W_src
    const float4 wd = reinterpret_cast<const float4*>(W + IN_DIMS)[lane];   // W_dst

    // Batch all row loads (independent -> MLP=4 per thread, 16 lines/warp in flight)
    float4 xa[ROWS_PER_WARP];
    #pragma unroll
    for (int r = 0; r < ROWS_PER_WARP; r++) {
        int row = row0 + r;
        if (row < n_nodes)
            xa[r] = reinterpret_cast<const float4*>(x + (size_t)row * IN_DIMS)[lane];
    }

    #pragma unroll
    for (int r = 0; r < ROWS_PER_WARP; r++) {
        int row = row0 + r;
        if (row >= n_nodes) break;
        float ps = xa[r].x * ws.x + xa[r].y * ws.y + xa[r].z * ws.z + xa[r].w * ws.w;
        float pt = xa[r].x * wd.x + xa[r].y * wd.y + xa[r].z * wd.z + xa[r].w * wd.w;
        #pragma unroll
        for (int o = 16; o > 0; o >>= 1) {
            ps += __shfl_xor_sync(0xffffffffu, ps, o);
            pt += __shfl_xor_sync(0xffffffffu, pt, o);
        }
        if (lane == 0) {
            g_s[row] = ps;
            g_t[row] = pt;
        }
    }
}

// 2 edges per thread: out[e] = s[src[e]] + t[dst[e]] + b
// edge_index is int32. 2/thread doubles resident warps vs 4/thread
// (full occupancy) while keeping identical gather-wavefront cost.
__global__ void edge_gather_kernel(const int* __restrict__ ei,
                                   const float* __restrict__ b,
                                   float* __restrict__ out,
                                   int n_edges) {
    int t = blockIdx.x * blockDim.x + threadIdx.x;
    int e = t * 2;
    if (e >= n_edges) return;
    float bias = __ldg(b);

    int2 si = *reinterpret_cast<const int2*>(ei + e);
    int2 di = *reinterpret_cast<const int2*>(ei + n_edges + e);
    float2 r;
    r.x = __ldg(&g_s[si.x]) + __ldg(&g_t[di.x]) + bias;
    r.y = __ldg(&g_s[si.y]) + __ldg(&g_t[di.y]) + bias;
    *reinterpret_cast<float2*>(out + e) = r;
}

extern "C" void kernel_launch(void* const* d_in, const int* in_sizes, int n_in,
                              void* d_out, int out_size) {
    const float* x   = (const float*)d_in[0];   // [N_NODES, 128] f32
    const int*   ei  = (const int*)d_in[1];     // [2, N_EDGES] int32
    const float* W   = (const float*)d_in[2];   // [1, 256] f32
    const float* b   = (const float*)d_in[3];   // [1] f32
    float*       out = (float*)d_out;           // [N_EDGES] f32

    // Node pass: 4 rows per warp, 8 warps/block.
    {
        int threads = 256;
        int warps = (N_NODES + ROWS_PER_WARP - 1) / ROWS_PER_WARP;   // 12500
        int blocks = (warps * 32 + threads - 1) / threads;           // 1563
        node_dot_kernel<<<blocks, threads>>>(x, W, N_NODES);
    }
    // Edge pass: 2 edges/thread.
    {
        int threads = 256;
        int total_threads = N_EDGES / 2;                              // 312500
        int blocks = (total_threads + threads - 1) / threads;         // 1221
        edge_gather_kernel<<<blocks, threads>>>(ei, b, out, N_EDGES);
    }
}

// round 7
// speedup vs baseline: 1.3434x; 1.1629x over previous
#include <cuda_runtime.h>
#include <cuda_fp16.h>
#include <stdint.h>

#define N_NODES 50000
#define N_EDGES 625000
#define IN_DIMS 128
#define ROWS_PER_WARP 8

#define EDGE_THREADS 512
#define EDGE_GRID 152
#define EDGE_CHUNK ((N_EDGES + EDGE_GRID - 1) / EDGE_GRID)   // 4112
#define EDGE_ITERS 5                                          // ceil(4112 / (512*2))
#define TABLE_BYTES (N_NODES * 4)                             // half2 per node = 200000 B

// Interleaved per-node table: {s = x.W_src, t = x.W_dst} as fp16.
__device__ __align__(16) __half2 g_st[N_NODES];

// ---------------- node pass: 8 rows per warp, loads batched for MLP ----------------
__global__ void node_dot_kernel(const float* __restrict__ x,
                                const float* __restrict__ W) {
    int warp = (int)((blockIdx.x * blockDim.x + threadIdx.x) >> 5);
    int lane = threadIdx.x & 31;
    int row0 = warp * ROWS_PER_WARP;
    if (row0 >= N_NODES) return;

    const float4 ws = reinterpret_cast<const float4*>(W)[lane];             // W_src
    const float4 wd = reinterpret_cast<const float4*>(W + IN_DIMS)[lane];   // W_dst

    float4 xa[ROWS_PER_WARP];
    #pragma unroll
    for (int r = 0; r < ROWS_PER_WARP; r++) {
        int row = row0 + r;
        if (row < N_NODES)
            xa[r] = reinterpret_cast<const float4*>(x + (size_t)row * IN_DIMS)[lane];
    }

    #pragma unroll
    for (int r = 0; r < ROWS_PER_WARP; r++) {
        int row = row0 + r;
        if (row >= N_NODES) break;
        float ps = fmaf(xa[r].x, ws.x, fmaf(xa[r].y, ws.y, fmaf(xa[r].z, ws.z, xa[r].w * ws.w)));
        float pt = fmaf(xa[r].x, wd.x, fmaf(xa[r].y, wd.y, fmaf(xa[r].z, wd.z, xa[r].w * wd.w)));
        #pragma unroll
        for (int o = 16; o > 0; o >>= 1) {
            ps += __shfl_xor_sync(0xffffffffu, ps, o);
            pt += __shfl_xor_sync(0xffffffffu, pt, o);
        }
        if (lane == 0)
            g_st[row] = make_half2(__float2half_rn(ps), __float2half_rn(pt));
    }
}

// ---------------- edge pass: persistent blocks, table staged in smem ----------------
__global__ __launch_bounds__(EDGE_THREADS, 1)
void edge_gather_kernel(const int* __restrict__ ei,
                        const float* __restrict__ b,
                        float* __restrict__ out) {
    extern __shared__ __half2 st[];
    int tid = threadIdx.x;
    int base = blockIdx.x * EDGE_CHUNK;
    int end  = min(base + EDGE_CHUNK, N_EDGES);

    // 1) Prefetch this thread's edge indices (independent LDGs, overlap with fill).
    int2 si[EDGE_ITERS], di[EDGE_ITERS];
    #pragma unroll
    for (int i = 0; i < EDGE_ITERS; i++) {
        int e = base + (i * EDGE_THREADS + tid) * 2;   // even; N_EDGES even -> int2 safe
        if (e < end) {
            si[i] = *reinterpret_cast<const int2*>(ei + e);
            di[i] = *reinterpret_cast<const int2*>(ei + N_EDGES + e);
        } else {
            si[i] = make_int2(0, 0);
            di[i] = make_int2(0, 0);
        }
    }

    // 2) Fill smem table with cp.async (16B chunks, no register round-trip).
    {
        uint32_t s_base;
        asm("{ .reg .u64 t; cvta.to.shared.u64 t, %1; cvt.u32.u64 %0, t; }"
            : "=r"(s_base) : "l"(st));
        const char* g_base = reinterpret_cast<const char*>(g_st);
        const int n_chunks = TABLE_BYTES / 16;   // 12500
        for (int c = tid; c < n_chunks; c += EDGE_THREADS) {
            asm volatile("cp.async.cg.shared.global [%0], [%1], 16;"
                         :: "r"(s_base + c * 16), "l"(g_base + (size_t)c * 16));
        }
        asm volatile("cp.async.commit_group;");
        asm volatile("cp.async.wait_group 0;" ::: "memory");
    }
    float bias = __ldg(b);
    __syncthreads();

    // 3) Gather from smem, compute, store.
    #pragma unroll
    for (int i = 0; i < EDGE_ITERS; i++) {
        int e = base + (i * EDGE_THREADS + tid) * 2;
        if (e < end) {
            __half2 a0 = st[si[i].x];
            __half2 c0 = st[di[i].x];
            __half2 a1 = st[si[i].y];
            __half2 c1 = st[di[i].y];
            float2 r;
            r.x = __low2float(a0) + __high2float(c0) + bias;
            r.y = __low2float(a1) + __high2float(c1) + bias;
            *reinterpret_cast<float2*>(out + e) = r;
        }
    }
}

extern "C" void kernel_launch(void* const* d_in, const int* in_sizes, int n_in,
                              void* d_out, int out_size) {
    const float* x   = (const float*)d_in[0];   // [N_NODES, 128] f32
    const int*   ei  = (const int*)d_in[1];     // [2, N_EDGES] int32
    const float* W   = (const float*)d_in[2];   // [1, 256] f32
    const float* b   = (const float*)d_in[3];   // [1] f32
    float*       out = (float*)d_out;           // [N_EDGES] f32

    static bool configured = false;
    if (!configured) {
        cudaFuncSetAttribute(edge_gather_kernel,
                             cudaFuncAttributeMaxDynamicSharedMemorySize, TABLE_BYTES);
        configured = true;
    }

    // Node pass: 8 rows/warp, 256 threads/block.
    {
        int threads = 256;
        int warps = (N_NODES + ROWS_PER_WARP - 1) / ROWS_PER_WARP;   // 6250
        int blocks = (warps * 32 + threads - 1) / threads;
        node_dot_kernel<<<blocks, threads>>>(x, W);
    }
    // Edge pass: persistent, one block per SM, table in smem.
    edge_gather_kernel<<<EDGE_GRID, EDGE_THREADS, TABLE_BYTES>>>(ei, b, out);
}